// round 10
// baseline (speedup 1.0000x reference)
#include <cuda_runtime.h>
#include <math.h>

#define NOISE_SCALE 0.1f
#define NOISE_RATIO 0.3f
#define ADAPTIVE_FACTOR 1.0f
#define MAX_NOISE 1.0f

#define B_ROWS 4096
#define D_COLS 4096
#define C_CLASSES 1000
#define C4 (C_CLASSES / 4)   // 250 float4 per model_output row
#define D4 (D_COLS / 4)      // 1024 float4 per data row
#define NCHUNK (D4 / 256)    // 4 chunks of 256 float4 per row
#define GRID 608             // 152 SMs * 4 resident blocks (persistent)

// Persistent one-block-per-row loop. Per row: prefetch ALL 12 elementwise
// LDG.128 + logits slice, single-barrier softmax-confidence reduction
// overlapped with the loads, apply + streaming store. Next row's logits
// slice is prefetched during the store phase.
__global__ __launch_bounds__(256) void fused_kernel(const float4* __restrict__ x,
                                                    const float4* __restrict__ mo4,
                                                    const float4* __restrict__ ru,
                                                    const float4* __restrict__ ns,
                                                    float4* __restrict__ out) {
    const int tid = threadIdx.x;
    const int lane = tid & 31;
    const int warp = tid >> 5;
    const bool have = (tid < C4);

    __shared__ float sm_m[8];   // per-warp max
    __shared__ float sm_s[8];   // per-warp sum of exp(l - m_w)

    // prefetch first row's logits slice
    int row = blockIdx.x;
    float4 v;
    if (have) v = __ldcs(&mo4[(long long)row * C4 + tid]);
    else      v = make_float4(-INFINITY, -INFINITY, -INFINITY, -INFINITY);

    for (; row < B_ROWS; ) {
        // ---- 1) prefetch all elementwise chunks (12 LDG.128 in flight) ----
        const long long base = (long long)row * D4;
        float4 xv[NCHUNK], rv[NCHUNK], nv[NCHUNK];
        #pragma unroll
        for (int j = 0; j < NCHUNK; j++) {
            const long long i = base + tid + j * 256;
            xv[j] = __ldcs(&x[i]);
            rv[j] = __ldcs(&ru[i]);
            nv[j] = __ldcs(&ns[i]);
        }

        // ---- 2) warp max tree, then sum-of-exp tree (overlaps loads) ----
        float m = fmaxf(fmaxf(v.x, v.y), fmaxf(v.z, v.w));
        #pragma unroll
        for (int off = 16; off >= 1; off >>= 1)
            m = fmaxf(m, __shfl_xor_sync(0xffffffffu, m, off));  // warp max (uniform)

        float s = have ? (__expf(v.x - m) + __expf(v.y - m) +
                          __expf(v.z - m) + __expf(v.w - m))
                       : 0.0f;
        #pragma unroll
        for (int off = 16; off >= 1; off >>= 1)
            s += __shfl_xor_sync(0xffffffffu, s, off);

        if (lane == 0) { sm_m[warp] = m; sm_s[warp] = s; }

        // v is consumed — prefetch next row's logits slice now, so its DRAM
        // latency hides behind the combine + store phase.
        const int next_row = row + GRID;
        if (next_row < B_ROWS) {
            if (have) v = __ldcs(&mo4[(long long)next_row * C4 + tid]);
        }

        __syncthreads();

        // ---- 3) every thread combines the 8 warp partials ----
        float M = sm_m[0];
        #pragma unroll
        for (int w = 1; w < 8; w++) M = fmaxf(M, sm_m[w]);
        float S = 0.0f;
        #pragma unroll
        for (int w = 0; w < 8; w++) S += sm_s[w] * __expf(sm_m[w] - M);
        const float conf = 1.0f / S;
        const float scale = fminf(NOISE_SCALE * (1.0f + ADAPTIVE_FACTOR * conf), MAX_NOISE);

        __syncthreads();   // protect sm_m/sm_s before next iteration overwrites

        // ---- 4) apply + store (data already resident in registers) ----
        #pragma unroll
        for (int j = 0; j < NCHUNK; j++) {
            const long long i = base + tid + j * 256;
            float4 o;
            o.x = xv[j].x + (rv[j].x < NOISE_RATIO ? nv[j].x * scale : 0.0f);
            o.y = xv[j].y + (rv[j].y < NOISE_RATIO ? nv[j].y * scale : 0.0f);
            o.z = xv[j].z + (rv[j].z < NOISE_RATIO ? nv[j].z * scale : 0.0f);
            o.w = xv[j].w + (rv[j].w < NOISE_RATIO ? nv[j].w * scale : 0.0f);
            __stcs(&out[i], o);
        }

        row = next_row;
    }
}

extern "C" void kernel_launch(void* const* d_in, const int* in_sizes, int n_in,
                              void* d_out, int out_size) {
    const float* x  = (const float*)d_in[0];
    const float* mo = (const float*)d_in[1];
    const float* ru = (const float*)d_in[2];
    const float* ns = (const float*)d_in[3];
    float* out = (float*)d_out;

    fused_kernel<<<GRID, 256>>>((const float4*)x, (const float4*)mo,
                                (const float4*)ru, (const float4*)ns,
                                (float4*)out);
}

// round 11
// speedup vs baseline: 1.2093x; 1.2093x over previous
#include <cuda_runtime.h>
#include <math.h>

#define NOISE_SCALE 0.1f
#define NOISE_RATIO 0.3f
#define ADAPTIVE_FACTOR 1.0f
#define MAX_NOISE 1.0f

#define B_ROWS 4096
#define D_COLS 4096
#define C_CLASSES 1000
#define C4 (C_CLASSES / 4)   // 250 float4 per model_output row
#define D4 (D_COLS / 4)      // 1024 float4 per data row
#define NCHUNK 2             // half-row per block: 2 chunks of 256 float4

// Two blocks per row: each block redundantly computes the row's softmax
// confidence (second block's logits read hits L2) but streams only HALF the
// elementwise row. Smaller register footprint -> 5+ CTAs/SM -> better
// latency hiding at the same front-batched-MLP structure.
__global__ __launch_bounds__(256) void fused_kernel(const float4* __restrict__ x,
                                                    const float4* __restrict__ mo4,
                                                    const float4* __restrict__ ru,
                                                    const float4* __restrict__ ns,
                                                    float4* __restrict__ out) {
    const int row  = blockIdx.x >> 1;
    const int half = blockIdx.x & 1;
    const int tid = threadIdx.x;
    const int lane = tid & 31;
    const int warp = tid >> 5;

    __shared__ float sm_m[8];   // per-warp max
    __shared__ float sm_s[8];   // per-warp sum of exp(l - m_w)

    // ---- 1) logits slice first (reduction depends only on this) ----
    float4 v;
    const bool have = (tid < C4);
    if (have) v = mo4[row * C4 + tid];
    else      v = make_float4(-INFINITY, -INFINITY, -INFINITY, -INFINITY);

    // ---- 2) prefetch this block's half-row (6 LDG.128 in flight) ----
    const int base = row * D4 + half * (D4 / 2) + tid;   // fits in int
    float4 xv[NCHUNK], rv[NCHUNK], nv[NCHUNK];
    #pragma unroll
    for (int j = 0; j < NCHUNK; j++) {
        const int i = base + j * 256;
        xv[j] = __ldcs(&x[i]);
        rv[j] = __ldcs(&ru[i]);
        nv[j] = __ldcs(&ns[i]);
    }

    // ---- 3) warp max tree, then sum-of-exp tree (overlaps load latency) ----
    float m = fmaxf(fmaxf(v.x, v.y), fmaxf(v.z, v.w));
    #pragma unroll
    for (int off = 16; off >= 1; off >>= 1)
        m = fmaxf(m, __shfl_xor_sync(0xffffffffu, m, off));  // warp max (uniform)

    float s = have ? (__expf(v.x - m) + __expf(v.y - m) +
                      __expf(v.z - m) + __expf(v.w - m))
                   : 0.0f;
    #pragma unroll
    for (int off = 16; off >= 1; off >>= 1)
        s += __shfl_xor_sync(0xffffffffu, s, off);

    if (lane == 0) { sm_m[warp] = m; sm_s[warp] = s; }
    __syncthreads();

    // ---- 4) every thread combines the 8 warp partials (no 2nd barrier) ----
    float M = sm_m[0];
    #pragma unroll
    for (int w = 1; w < 8; w++) M = fmaxf(M, sm_m[w]);
    float S = 0.0f;
    #pragma unroll
    for (int w = 0; w < 8; w++) S += sm_s[w] * __expf(sm_m[w] - M);
    const float conf = 1.0f / S;
    const float scale = fminf(NOISE_SCALE * (1.0f + ADAPTIVE_FACTOR * conf), MAX_NOISE);

    // ---- 5) apply + store (data already resident in registers) ----
    #pragma unroll
    for (int j = 0; j < NCHUNK; j++) {
        const int i = base + j * 256;
        float4 o;
        o.x = xv[j].x + (rv[j].x < NOISE_RATIO ? nv[j].x * scale : 0.0f);
        o.y = xv[j].y + (rv[j].y < NOISE_RATIO ? nv[j].y * scale : 0.0f);
        o.z = xv[j].z + (rv[j].z < NOISE_RATIO ? nv[j].z * scale : 0.0f);
        o.w = xv[j].w + (rv[j].w < NOISE_RATIO ? nv[j].w * scale : 0.0f);
        __stcs(&out[i], o);
    }
}

extern "C" void kernel_launch(void* const* d_in, const int* in_sizes, int n_in,
                              void* d_out, int out_size) {
    const float* x  = (const float*)d_in[0];
    const float* mo = (const float*)d_in[1];
    const float* ru = (const float*)d_in[2];
    const float* ns = (const float*)d_in[3];
    float* out = (float*)d_out;

    fused_kernel<<<B_ROWS * 2, 256>>>((const float4*)x, (const float4*)mo,
                                      (const float4*)ru, (const float4*)ns,
                                      (float4*)out);
}